// round 9
// baseline (speedup 1.0000x reference)
#include <cuda_runtime.h>
#include <mma.h>
#include <cstdint>

using namespace nvcuda;

#define D_MODEL 1024
#define BATCH   4
#define SEQ     4096
#define M_TOTAL (BATCH*SEQ)
#define NX      (M_TOTAL*D_MODEL)      // 16M
#define D2      (D_MODEL*D_MODEL)      // 1M

#define CHUNK  64
#define NCHUNK (SEQ/CHUNK)   // 64

typedef signed char s8;

// ---------------- scratch (__device__ globals, allocation-free rule)
__device__ float g_max[4];                     // 0:x 1:W_up 2:W_f 3:u
__device__ s8    q_ahi[NX], q_alo[NX];         // activation hi/lo (x, then reused for u)
__device__ s8    q_w1hi[D2], q_w1lo[D2];
__device__ s8    q_w2hi[D2], q_w2lo[D2];
__device__ float g_buf[NX];                    // u after GEMM1, then v after GEMM2
__device__ float g_C  [BATCH*NCHUNK*D_MODEL];
__device__ float g_cin[BATCH*NCHUNK*D_MODEL];

// ---------------- helpers
__device__ __forceinline__ uint32_t smem_u32(const void* p) {
    uint32_t a;
    asm("{ .reg .u64 t; cvta.to.shared.u64 t, %1; cvt.u32.u64 %0, t; }" : "=r"(a) : "l"(p));
    return a;
}
#define CP_ASYNC16(smem_addr, gptr) \
    asm volatile("cp.async.cg.shared.global [%0], [%1], 16;" :: "r"(smem_addr), "l"(gptr))
#define CP_COMMIT() asm volatile("cp.async.commit_group;" ::: "memory")
#define CP_WAIT(n)  asm volatile("cp.async.wait_group %0;" :: "n"(n) : "memory")

// ---------------- max-reduction + quantization
__global__ void reset_max() { if (threadIdx.x < 4) g_max[threadIdx.x] = 0.0f; }

__global__ __launch_bounds__(256) void rmax(const float4* __restrict__ src, int n4, int slot)
{
    float m = 0.0f;
    for (int i = blockIdx.x * blockDim.x + threadIdx.x; i < n4; i += gridDim.x * blockDim.x) {
        float4 v = src[i];
        m = fmaxf(m, fmaxf(fmaxf(fabsf(v.x), fabsf(v.y)), fmaxf(fabsf(v.z), fabsf(v.w))));
    }
    #pragma unroll
    for (int o = 16; o; o >>= 1) m = fmaxf(m, __shfl_xor_sync(0xFFFFFFFFu, m, o));
    if ((threadIdx.x & 31) == 0) atomicMax((int*)&g_max[slot], __float_as_int(m));
}

// v ~= s*(128*qhi + qlo), s = max/16256, |qhi|<=127, |qlo|<=64, |err|<=s/2
__global__ __launch_bounds__(256) void quantize(const float4* __restrict__ src,
                                                char4* __restrict__ qhi, char4* __restrict__ qlo,
                                                int n4, int slot)
{
    int i = blockIdx.x * blockDim.x + threadIdx.x;
    if (i >= n4) return;
    float inv = 16256.0f / fmaxf(g_max[slot], 1e-30f);
    float4 v = src[i];
    char4 h, l;
    {
        float q = v.x * inv; float fh = rintf(q * (1.0f/128.0f)); float fl = rintf(q - 128.0f * fh);
        h.x = (s8)(int)fh; l.x = (s8)(int)fl;
    }
    {
        float q = v.y * inv; float fh = rintf(q * (1.0f/128.0f)); float fl = rintf(q - 128.0f * fh);
        h.y = (s8)(int)fh; l.y = (s8)(int)fl;
    }
    {
        float q = v.z * inv; float fh = rintf(q * (1.0f/128.0f)); float fl = rintf(q - 128.0f * fh);
        h.z = (s8)(int)fh; l.z = (s8)(int)fl;
    }
    {
        float q = v.w * inv; float fh = rintf(q * (1.0f/128.0f)); float fl = rintf(q - 128.0f * fh);
        h.w = (s8)(int)fh; l.w = (s8)(int)fl;
    }
    qhi[i] = h; qlo[i] = l;
}

// ---------------- split-int8 GEMM:  out[m,n] = (sA*sB*(16384*acc_hh + 128*acc_cross) + bias[n]) * mask?[m]
#define BM 128
#define BN 128
#define BK 32
#define LDT8 48                       // int8 smem row stride (mult of 16)
#define TILE_B (128*LDT8)             // 6144 B
#define STAGE_B (4*TILE_B)            // 24576 B (Ahi,Alo,Bhi,Blo)
#define STAGES 3
#define SMEM_BYTES (STAGES*STAGE_B)   // 73728 B
#define LDC 136
#define KITERS (D_MODEL/BK)           // 32

extern __shared__ unsigned char sm8[];

__global__ __launch_bounds__(256, 1)
void gemm_i8(const s8* __restrict__ Ahi, const s8* __restrict__ Alo,
             const s8* __restrict__ Bhi, const s8* __restrict__ Blo,
             const float* __restrict__ bias, const float* __restrict__ mask,
             float* __restrict__ out, int slotA, int slotB)
{
    const int tid    = threadIdx.x;
    const int warp   = tid >> 5;
    const int warp_m = warp & 3;   // 4 row tiles of 32
    const int warp_n = warp >> 2;  // 2 col tiles of 64
    const int m0 = blockIdx.y * BM;
    const int n0 = blockIdx.x * BN;

    const uint32_t sbase = smem_u32(sm8);
    const int r  = tid >> 1;           // 0..127
    const int co = (tid & 1) << 4;     // 0,16

    auto issue = [&](int ki, int buf) {
        const int k0 = ki * BK;
        uint32_t s0 = sbase + (uint32_t)(buf * STAGE_B + r * LDT8 + co);
        size_t ga = (size_t)(m0 + r) * D_MODEL + k0 + co;
        size_t gb = (size_t)(n0 + r) * D_MODEL + k0 + co;
        CP_ASYNC16(s0 + 0u*TILE_B, Ahi + ga);
        CP_ASYNC16(s0 + 1u*TILE_B, Alo + ga);
        CP_ASYNC16(s0 + 2u*TILE_B, Bhi + gb);
        CP_ASYNC16(s0 + 3u*TILE_B, Blo + gb);
    };

    wmma::fragment<wmma::accumulator, 16, 16, 16, int> acc1[2][4], acc2[2][4];
    #pragma unroll
    for (int i = 0; i < 2; i++)
        #pragma unroll
        for (int j = 0; j < 4; j++) {
            wmma::fill_fragment(acc1[i][j], 0);
            wmma::fill_fragment(acc2[i][j], 0);
        }

    #pragma unroll
    for (int s = 0; s < STAGES - 1; s++) { issue(s, s); CP_COMMIT(); }

    for (int i = 0; i < KITERS; i++) {
        CP_WAIT(1);
        __syncthreads();

        if (i + STAGES - 1 < KITERS) issue(i + STAGES - 1, (i + STAGES - 1) % STAGES);
        CP_COMMIT();

        const unsigned char* stg = sm8 + (i % STAGES) * STAGE_B;
        const s8* As_hi = (const s8*)(stg + 0*TILE_B);
        const s8* As_lo = (const s8*)(stg + 1*TILE_B);
        const s8* Bs_hi = (const s8*)(stg + 2*TILE_B);
        const s8* Bs_lo = (const s8*)(stg + 3*TILE_B);

        #pragma unroll
        for (int kk = 0; kk < BK; kk += 16) {
            wmma::fragment<wmma::matrix_a, 16, 16, 16, s8, wmma::row_major> ah[2], al[2];
            wmma::fragment<wmma::matrix_b, 16, 16, 16, s8, wmma::col_major> bh[4], bl[4];
            #pragma unroll
            for (int a = 0; a < 2; a++) {
                int ro = (warp_m * 32 + a * 16) * LDT8 + kk;
                wmma::load_matrix_sync(ah[a], As_hi + ro, LDT8);
                wmma::load_matrix_sync(al[a], As_lo + ro, LDT8);
            }
            #pragma unroll
            for (int b = 0; b < 4; b++) {
                int ro = (warp_n * 64 + b * 16) * LDT8 + kk;
                wmma::load_matrix_sync(bh[b], Bs_hi + ro, LDT8);
                wmma::load_matrix_sync(bl[b], Bs_lo + ro, LDT8);
            }
            #pragma unroll
            for (int a = 0; a < 2; a++)
                #pragma unroll
                for (int b = 0; b < 4; b++) {
                    wmma::mma_sync(acc1[a][b], ah[a], bh[b], acc1[a][b]);  // hi*hi   (scale 16384)
                    wmma::mma_sync(acc2[a][b], al[a], bh[b], acc2[a][b]);  // lo*hi   (scale 128)
                    wmma::mma_sync(acc2[a][b], ah[a], bl[b], acc2[a][b]);  // hi*lo   (scale 128)
                }
        }
    }
    __syncthreads();

    // Epilogue: two 64-row stages through smem (int32 staging x2), fuse dequant+bias+mask.
    const float sA  = fmaxf(g_max[slotA], 1e-30f) * (1.0f/16256.0f);
    const float sB  = fmaxf(g_max[slotB], 1e-30f) * (1.0f/16256.0f);
    const float sc1 = 16384.0f * sA * sB;
    const float sc2 = 128.0f   * sA * sB;

    int* Cs1 = (int*)sm8;
    int* Cs2 = Cs1 + 64 * LDC;

    #pragma unroll
    for (int stage = 0; stage < 2; stage++) {
        if ((warp_m >> 1) == stage) {
            int rbase = (warp_m & 1) * 32;
            #pragma unroll
            for (int a = 0; a < 2; a++)
                #pragma unroll
                for (int b = 0; b < 4; b++) {
                    int o = (rbase + a * 16) * LDC + warp_n * 64 + b * 16;
                    wmma::store_matrix_sync(Cs1 + o, acc1[a][b], LDC, wmma::mem_row_major);
                    wmma::store_matrix_sync(Cs2 + o, acc2[a][b], LDC, wmma::mem_row_major);
                }
        }
        __syncthreads();
        #pragma unroll
        for (int it = 0; it < 8; it++) {
            int idx = (tid + it * 256) << 2;    // 0..8188
            int rr = idx >> 7;                  // 0..63
            int cc = idx & 127;
            int gm = m0 + stage * 64 + rr;
            int gn = n0 + cc;
            int4 c1 = *(const int4*)(Cs1 + rr * LDC + cc);
            int4 c2 = *(const int4*)(Cs2 + rr * LDC + cc);
            float4 bb = bias ? *(const float4*)(bias + gn) : make_float4(0.f, 0.f, 0.f, 0.f);
            float mv = mask ? mask[gm] : 1.0f;
            float4 v;
            v.x = (sc1 * (float)c1.x + sc2 * (float)c2.x + bb.x) * mv;
            v.y = (sc1 * (float)c1.y + sc2 * (float)c2.y + bb.y) * mv;
            v.z = (sc1 * (float)c1.z + sc2 * (float)c2.z + bb.z) * mv;
            v.w = (sc1 * (float)c1.w + sc2 * (float)c2.w + bb.w) * mv;
            *(float4*)(out + (size_t)gm * D_MODEL + gn) = v;
        }
        __syncthreads();
    }
}

// ---------------- Decay scan on g_buf (h_t = decay*h_{t-1} + v_t), chunked 3-pass
__device__ __forceinline__ float get_decay(const float* dp) {
    return 1.0f / (1.0f + expf(-dp[0]));
}

__global__ __launch_bounds__(256) void scan_pass1(const float* __restrict__ dp)
{
    float decay = get_decay(dp);
    int e = blockIdx.x * 256 + threadIdx.x;
    int c = blockIdx.y;
    int b = blockIdx.z;
    const float* u = g_buf + ((size_t)(b * SEQ + c * CHUNK)) * D_MODEL + e;
    float h = 0.0f;
    #pragma unroll 8
    for (int s = 0; s < CHUNK; s++)
        h = fmaf(decay, h, u[(size_t)s * D_MODEL]);
    g_C[((size_t)b * NCHUNK + c) * D_MODEL + e] = h;
}

__global__ __launch_bounds__(256) void scan_pass2(const float* __restrict__ dp)
{
    float decay = get_decay(dp);
    float dpow = decay;
    #pragma unroll
    for (int i = 0; i < 6; i++) dpow *= dpow;  // decay^64
    int idx = blockIdx.x * 256 + threadIdx.x;
    int b = idx >> 10;
    int e = idx & 1023;
    float he = 0.0f;
    #pragma unroll 4
    for (int c = 0; c < NCHUNK; c++) {
        size_t off = ((size_t)b * NCHUNK + c) * D_MODEL + e;
        g_cin[off] = he;
        he = fmaf(dpow, he, g_C[off]);
    }
}

__global__ __launch_bounds__(256) void scan_pass3(const float* __restrict__ dp,
                                                  const float* __restrict__ bias,
                                                  float* __restrict__ dst)
{
    float decay = get_decay(dp);
    int e = blockIdx.x * 256 + threadIdx.x;
    int c = blockIdx.y;
    int b = blockIdx.z;
    size_t base = ((size_t)(b * SEQ + c * CHUNK)) * D_MODEL + e;
    const float* u = g_buf + base;
    float*       o = dst  + base;
    float bf = bias[e];
    float acc = g_cin[((size_t)b * NCHUNK + c) * D_MODEL + e];
    #pragma unroll 8
    for (int s = 0; s < CHUNK; s++) {
        acc = fmaf(decay, acc, u[(size_t)s * D_MODEL]);
        o[(size_t)s * D_MODEL] = acc + bf;
    }
}

// ---------------- launch
extern "C" void kernel_launch(void* const* d_in, const int* in_sizes, int n_in,
                              void* d_out, int out_size)
{
    const float* x     = (const float*)d_in[0];
    const float* mask  = (const float*)d_in[1];
    const float* W_up  = (const float*)d_in[2];
    const float* b_up  = (const float*)d_in[3];
    const float* W_f   = (const float*)d_in[4];
    const float* b_f   = (const float*)d_in[5];
    const float* dp    = (const float*)d_in[6];
    float* out = (float*)d_out;

    s8 *ahi, *alo, *w1h, *w1l, *w2h, *w2l;
    cudaGetSymbolAddress((void**)&ahi, q_ahi);
    cudaGetSymbolAddress((void**)&alo, q_alo);
    cudaGetSymbolAddress((void**)&w1h, q_w1hi);
    cudaGetSymbolAddress((void**)&w1l, q_w1lo);
    cudaGetSymbolAddress((void**)&w2h, q_w2hi);
    cudaGetSymbolAddress((void**)&w2l, q_w2lo);
    float* buf;
    cudaGetSymbolAddress((void**)&buf, g_buf);

    cudaFuncSetAttribute(gemm_i8, cudaFuncAttributeMaxDynamicSharedMemorySize, SMEM_BYTES);

    dim3 ggrid(D_MODEL / BN, M_TOTAL / BM);   // (8, 128)

    // quantize inputs
    reset_max<<<1, 32>>>();
    rmax<<<1024, 256>>>((const float4*)x,    NX / 4, 0);
    rmax<<<256,  256>>>((const float4*)W_up, D2 / 4, 1);
    rmax<<<256,  256>>>((const float4*)W_f,  D2 / 4, 2);
    quantize<<<NX / 4 / 256, 256>>>((const float4*)x,    (char4*)ahi, (char4*)alo, NX / 4, 0);
    quantize<<<D2 / 4 / 256, 256>>>((const float4*)W_up, (char4*)w1h, (char4*)w1l, D2 / 4, 1);
    quantize<<<D2 / 4 / 256, 256>>>((const float4*)W_f,  (char4*)w2h, (char4*)w2l, D2 / 4, 2);

    // u = (x @ W_up^T + b_up) * mask
    gemm_i8<<<ggrid, 256, SMEM_BYTES>>>(ahi, alo, w1h, w1l, b_up, mask, buf, 0, 1);

    // quantize u (reuse activation buffers)
    rmax<<<1024, 256>>>((const float4*)buf, NX / 4, 3);
    quantize<<<NX / 4 / 256, 256>>>((const float4*)buf, (char4*)ahi, (char4*)alo, NX / 4, 3);

    // v = u @ W_f^T   (scan commutes with the linear map: out = scan(v) + b_f)
    gemm_i8<<<ggrid, 256, SMEM_BYTES>>>(ahi, alo, w2h, w2l, nullptr, nullptr, buf, 3, 2);

    // out = scan(v) + b_f
    scan_pass1<<<dim3(4, NCHUNK, BATCH), 256>>>(dp);
    scan_pass2<<<16, 256>>>(dp);
    scan_pass3<<<dim3(4, NCHUNK, BATCH), 256>>>(dp, b_f, out);
}

// round 10
// speedup vs baseline: 10.0633x; 10.0633x over previous
#include <cuda_runtime.h>
#include <cuda_fp16.h>
#include <mma.h>
#include <cstdint>

using namespace nvcuda;

#define D_MODEL 1024
#define BATCH   4
#define SEQ     4096
#define M_TOTAL (BATCH*SEQ)
#define NX      (M_TOTAL*D_MODEL)      // 16M
#define D2      (D_MODEL*D_MODEL)      // 1M

#define CHUNK  64
#define NCHUNK (SEQ/CHUNK)   // 64

// ---------------- scratch (__device__ globals, allocation-free rule)
__device__ __half g_xh[NX];            // x (half), then reused? no: keep separate
__device__ __half g_uh[NX];            // u (half) after GEMM1
__device__ __half g_w1h[D2];
__device__ __half g_w2h[D2];
__device__ float  g_buf[NX];           // v after GEMM2
__device__ float  g_C  [BATCH*NCHUNK*D_MODEL];
__device__ float  g_cin[BATCH*NCHUNK*D_MODEL];

// ---------------- helpers
__device__ __forceinline__ uint32_t smem_u32(const void* p) {
    uint32_t a;
    asm("{ .reg .u64 t; cvta.to.shared.u64 t, %1; cvt.u32.u64 %0, t; }" : "=r"(a) : "l"(p));
    return a;
}
#define CP_ASYNC16(smem_addr, gptr) \
    asm volatile("cp.async.cg.shared.global [%0], [%1], 16;" :: "r"(smem_addr), "l"(gptr))
#define CP_COMMIT() asm volatile("cp.async.commit_group;" ::: "memory")
#define CP_WAIT(n)  asm volatile("cp.async.wait_group %0;" :: "n"(n) : "memory")

// ---------------- f32 -> f16 conversion (vectorized)
__global__ __launch_bounds__(256) void to_half(const float4* __restrict__ src,
                                               __half2* __restrict__ dst, int n4)
{
    int i = blockIdx.x * blockDim.x + threadIdx.x;
    if (i >= n4) return;
    float4 v = src[i];
    dst[2*i + 0] = __floats2half2_rn(v.x, v.y);
    dst[2*i + 1] = __floats2half2_rn(v.z, v.w);
}

// ---------------- fp16 wmma GEMM, 3-stage cp.async pipeline
// acc[m,n] = sum_d A[m,d]*W[n,d]; then:
//   out_h != 0 : out_h[m,n] = half((acc + bias[n]) * mask?[m])
//   else       : out_f[m,n] = acc
#define BM 128
#define BN 128
#define BK 32
#define LDT_H 40                         // half stride (80B rows, 16B aligned)
#define TILE_H (128*LDT_H)               // halves per tile (5120) = 10240 B
#define STAGE_H (2*TILE_H)               // A + B
#define STAGES 3
#define SMEM_BYTES (STAGES*STAGE_H*2)    // 61440 B
#define LDC 136
#define KITERS (D_MODEL/BK)              // 32

extern __shared__ __half sm_h[];

__global__ __launch_bounds__(256, 2)
void gemm_h(const __half* __restrict__ A, const __half* __restrict__ W,
            const float* __restrict__ bias, const float* __restrict__ mask,
            __half* __restrict__ out_h, float* __restrict__ out_f)
{
    const int tid    = threadIdx.x;
    const int warp   = tid >> 5;
    const int warp_m = warp & 3;   // 4 row tiles of 32
    const int warp_n = warp >> 2;  // 2 col tiles of 64
    const int m0 = blockIdx.y * BM;
    const int n0 = blockIdx.x * BN;

    const uint32_t sbase = smem_u32(sm_h);

    // 128x32 halves per tile = 512 chunks of 8 halves; 256 threads -> 2 chunks/matrix.
    const int r_ld [2] = { (tid + 0)   >> 2, (tid + 256) >> 2 };
    const int c8_ld[2] = { ((tid + 0) & 3) << 3, ((tid + 256) & 3) << 3 };

    auto issue = [&](int ki, int buf) {
        const int k0 = ki * BK;
        const uint32_t sa = sbase + (uint32_t)(buf * STAGE_H) * 2u;
        const uint32_t sb = sa + TILE_H * 2u;
        #pragma unroll
        for (int j = 0; j < 2; j++) {
            int r = r_ld[j], c8 = c8_ld[j];
            uint32_t so = (uint32_t)(r * LDT_H + c8) * 2u;
            CP_ASYNC16(sa + so, A + (size_t)(m0 + r) * D_MODEL + k0 + c8);
            CP_ASYNC16(sb + so, W + (size_t)(n0 + r) * D_MODEL + k0 + c8);
        }
    };

    wmma::fragment<wmma::accumulator, 16, 16, 16, float> acc[2][4];
    #pragma unroll
    for (int i = 0; i < 2; i++)
        #pragma unroll
        for (int j = 0; j < 4; j++)
            wmma::fill_fragment(acc[i][j], 0.0f);

    #pragma unroll
    for (int s = 0; s < STAGES - 1; s++) { issue(s, s); CP_COMMIT(); }

    for (int i = 0; i < KITERS; i++) {
        CP_WAIT(1);
        __syncthreads();

        if (i + STAGES - 1 < KITERS) issue(i + STAGES - 1, (i + STAGES - 1) % STAGES);
        CP_COMMIT();

        const __half* As = sm_h + (i % STAGES) * STAGE_H;
        const __half* Bs = As + TILE_H;

        #pragma unroll
        for (int kk = 0; kk < BK; kk += 16) {
            wmma::fragment<wmma::matrix_a, 16, 16, 16, half, wmma::row_major> af[2];
            wmma::fragment<wmma::matrix_b, 16, 16, 16, half, wmma::col_major> bf[4];
            #pragma unroll
            for (int a = 0; a < 2; a++)
                wmma::load_matrix_sync(af[a], As + (warp_m * 32 + a * 16) * LDT_H + kk, LDT_H);
            #pragma unroll
            for (int b = 0; b < 4; b++)
                wmma::load_matrix_sync(bf[b], Bs + (warp_n * 64 + b * 16) * LDT_H + kk, LDT_H);
            #pragma unroll
            for (int a = 0; a < 2; a++)
                #pragma unroll
                for (int b = 0; b < 4; b++)
                    wmma::mma_sync(acc[a][b], af[a], bf[b], acc[a][b]);
        }
    }
    __syncthreads();

    // Epilogue: two 64-row stages through smem; fuse bias/mask; half or float output.
    float* Cs = (float*)sm_h;
    #pragma unroll
    for (int stage = 0; stage < 2; stage++) {
        if ((warp_m >> 1) == stage) {
            int rbase = (warp_m & 1) * 32;
            #pragma unroll
            for (int a = 0; a < 2; a++)
                #pragma unroll
                for (int b = 0; b < 4; b++)
                    wmma::store_matrix_sync(Cs + (rbase + a * 16) * LDC + warp_n * 64 + b * 16,
                                            acc[a][b], LDC, wmma::mem_row_major);
        }
        __syncthreads();
        #pragma unroll
        for (int it = 0; it < 8; it++) {
            int idx = (tid + it * 256) << 2;   // 0..8188
            int rr = idx >> 7;                 // 0..63
            int cc = idx & 127;
            int gm = m0 + stage * 64 + rr;
            int gn = n0 + cc;
            float4 v = *(const float4*)(Cs + rr * LDC + cc);
            if (out_h) {
                float4 bb = *(const float4*)(bias + gn);
                float mv = mask[gm];
                v.x = (v.x + bb.x) * mv;
                v.y = (v.y + bb.y) * mv;
                v.z = (v.z + bb.z) * mv;
                v.w = (v.w + bb.w) * mv;
                __half2* dst = (__half2*)(out_h + (size_t)gm * D_MODEL + gn);
                dst[0] = __floats2half2_rn(v.x, v.y);
                dst[1] = __floats2half2_rn(v.z, v.w);
            } else {
                *(float4*)(out_f + (size_t)gm * D_MODEL + gn) = v;
            }
        }
        __syncthreads();
    }
}

// ---------------- Decay scan on g_buf (h_t = decay*h_{t-1} + v_t), chunked 3-pass
__device__ __forceinline__ float get_decay(const float* dp) {
    return 1.0f / (1.0f + expf(-dp[0]));
}

__global__ __launch_bounds__(256) void scan_pass1(const float* __restrict__ dp)
{
    float decay = get_decay(dp);
    int e = blockIdx.x * 256 + threadIdx.x;
    int c = blockIdx.y;
    int b = blockIdx.z;
    const float* u = g_buf + ((size_t)(b * SEQ + c * CHUNK)) * D_MODEL + e;
    float h = 0.0f;
    #pragma unroll 8
    for (int s = 0; s < CHUNK; s++)
        h = fmaf(decay, h, u[(size_t)s * D_MODEL]);
    g_C[((size_t)b * NCHUNK + c) * D_MODEL + e] = h;
}

__global__ __launch_bounds__(256) void scan_pass2(const float* __restrict__ dp)
{
    float decay = get_decay(dp);
    float dpow = decay;
    #pragma unroll
    for (int i = 0; i < 6; i++) dpow *= dpow;  // decay^64
    int idx = blockIdx.x * 256 + threadIdx.x;
    int b = idx >> 10;
    int e = idx & 1023;
    float he = 0.0f;
    #pragma unroll 4
    for (int c = 0; c < NCHUNK; c++) {
        size_t off = ((size_t)b * NCHUNK + c) * D_MODEL + e;
        g_cin[off] = he;
        he = fmaf(dpow, he, g_C[off]);
    }
}

__global__ __launch_bounds__(256) void scan_pass3(const float* __restrict__ dp,
                                                  const float* __restrict__ bias,
                                                  float* __restrict__ dst)
{
    float decay = get_decay(dp);
    int e = blockIdx.x * 256 + threadIdx.x;
    int c = blockIdx.y;
    int b = blockIdx.z;
    size_t base = ((size_t)(b * SEQ + c * CHUNK)) * D_MODEL + e;
    const float* u = g_buf + base;
    float*       o = dst  + base;
    float bf = bias[e];
    float acc = g_cin[((size_t)b * NCHUNK + c) * D_MODEL + e];
    #pragma unroll 8
    for (int s = 0; s < CHUNK; s++) {
        acc = fmaf(decay, acc, u[(size_t)s * D_MODEL]);
        o[(size_t)s * D_MODEL] = acc + bf;
    }
}

// ---------------- launch
extern "C" void kernel_launch(void* const* d_in, const int* in_sizes, int n_in,
                              void* d_out, int out_size)
{
    const float* x     = (const float*)d_in[0];
    const float* mask  = (const float*)d_in[1];
    const float* W_up  = (const float*)d_in[2];
    const float* b_up  = (const float*)d_in[3];
    const float* W_f   = (const float*)d_in[4];
    const float* b_f   = (const float*)d_in[5];
    const float* dp    = (const float*)d_in[6];
    float* out = (float*)d_out;

    __half *xh, *uh, *w1h, *w2h;
    float* buf;
    cudaGetSymbolAddress((void**)&xh,  g_xh);
    cudaGetSymbolAddress((void**)&uh,  g_uh);
    cudaGetSymbolAddress((void**)&w1h, g_w1h);
    cudaGetSymbolAddress((void**)&w2h, g_w2h);
    cudaGetSymbolAddress((void**)&buf, g_buf);

    cudaFuncSetAttribute(gemm_h, cudaFuncAttributeMaxDynamicSharedMemorySize, SMEM_BYTES);

    dim3 ggrid(D_MODEL / BN, M_TOTAL / BM);   // (8, 128)

    // convert inputs to fp16
    to_half<<<NX / 4 / 256, 256>>>((const float4*)x,    (__half2*)xh,  NX / 4);
    to_half<<<D2 / 4 / 256, 256>>>((const float4*)W_up, (__half2*)w1h, D2 / 4);
    to_half<<<D2 / 4 / 256, 256>>>((const float4*)W_f,  (__half2*)w2h, D2 / 4);

    // u = half((x @ W_up^T + b_up) * mask)
    gemm_h<<<ggrid, 256, SMEM_BYTES>>>(xh, w1h, b_up, mask, uh, nullptr);

    // v = u @ W_f^T  (fp32 out; scan commutes with the linear map)
    gemm_h<<<ggrid, 256, SMEM_BYTES>>>(uh, w2h, nullptr, nullptr, nullptr, buf);

    // out = scan(v) + b_f
    scan_pass1<<<dim3(4, NCHUNK, BATCH), 256>>>(dp);
    scan_pass2<<<16, 256>>>(dp);
    scan_pass3<<<dim3(4, NCHUNK, BATCH), 256>>>(dp, b_f, out);
}